// round 15
// baseline (speedup 1.0000x reference)
#include <cuda_runtime.h>
#include <cuda_fp16.h>
#include <math.h>
#include <stdint.h>

#define DIM  1024
#define HID  2048
#define NE   8
#define MAXT 4096
#define MAXSLOTS (MAXT*2)

// ---------------- device scratch ----------------
__device__ int    g_counts[NE];
__device__ int    g_fill[NE];
__device__ int    g_tok_e[MAXT*2];
__device__ float  g_tok_w[MAXT*2];
__device__ int    g_slot_tok[MAXSLOTS];
__device__ float  g_slot_w[MAXSLOTS];
__device__ __half g_Xh[(size_t)MAXT*DIM];
__device__ __half g_H[(size_t)MAXSLOTS*HID];
__device__ __half g_W1T[(size_t)NE*HID*DIM];    // [E][HID][DIM] k-major
__device__ __half g_W3T[(size_t)NE*HID*DIM];
__device__ __half g_W2T[(size_t)NE*DIM*HID];    // [E][DIM][HID] k-major

// ---------------- helpers ----------------
__device__ __forceinline__ uint32_t smem_u32(const void* p) {
    uint32_t a;
    asm("{ .reg .u64 t; cvta.to.shared.u64 t, %1; cvt.u32.u64 %0, t; }" : "=r"(a) : "l"(p));
    return a;
}
__device__ __forceinline__ void cpa16(uint32_t dst, const void* src, int sz) {
    asm volatile("cp.async.cg.shared.global [%0], [%1], 16, %2;"
                 :: "r"(dst), "l"(src), "r"(sz) : "memory");
}
#define CP_COMMIT() asm volatile("cp.async.commit_group;" ::: "memory")
#define CP_WAIT1()  asm volatile("cp.async.wait_group 1;" ::: "memory")
#define CP_WAIT0()  asm volatile("cp.async.wait_group 0;" ::: "memory")

#define LDSM4(r, addr) \
    asm volatile("ldmatrix.sync.aligned.m8n8.x4.shared.b16 {%0,%1,%2,%3}, [%4];" \
        : "=r"((r)[0]), "=r"((r)[1]), "=r"((r)[2]), "=r"((r)[3]) : "r"(addr))

#define MMA_F16(d, a, b) \
    asm volatile("mma.sync.aligned.m16n8k16.row.col.f32.f16.f16.f32 " \
        "{%0,%1,%2,%3}, {%4,%5,%6,%7}, {%8,%9}, {%0,%1,%2,%3};" \
        : "+f"((d)[0]), "+f"((d)[1]), "+f"((d)[2]), "+f"((d)[3]) \
        : "r"((a)[0]), "r"((a)[1]), "r"((a)[2]), "r"((a)[3]), \
          "r"((b)[0]), "r"((b)[1]))

__device__ __forceinline__ int expert_base(int e) {
    int b = 0;
#pragma unroll
    for (int i = 0; i < NE; i++) b += (i < e) ? g_counts[i] : 0;
    return b;
}

__global__ void k_zero_cnt() {
    if (threadIdx.x < NE) { g_counts[threadIdx.x] = 0; g_fill[threadIdx.x] = 0; }
}

// ---------------- fused front: zero out, cvt x->fp16, route ----------------
__global__ __launch_bounds__(256) void k_front(
    const float* __restrict__ x, const float* __restrict__ Wg,
    float* __restrict__ out, int T)
{
    int b = blockIdx.x;
    if (b < 512) {
        int warp = (b * 256 + threadIdx.x) >> 5;
        int lane = threadIdx.x & 31;
        if (warp >= T) return;
        const float* xr = x + (size_t)warp * DIM;
        float acc[NE];
#pragma unroll
        for (int e = 0; e < NE; e++) acc[e] = 0.f;
        for (int i = lane; i < DIM; i += 32) {
            float xv = xr[i];
            const float* wg = Wg + (size_t)i * NE;
#pragma unroll
            for (int e = 0; e < NE; e++) acc[e] += xv * wg[e];
        }
#pragma unroll
        for (int off = 16; off > 0; off >>= 1)
#pragma unroll
            for (int e = 0; e < NE; e++)
                acc[e] += __shfl_down_sync(0xffffffffu, acc[e], off);
        if (lane == 0) {
            int i0 = 0; float s0 = acc[0];
#pragma unroll
            for (int e = 1; e < NE; e++) if (acc[e] > s0) { s0 = acc[e]; i0 = e; }
            int i1 = -1; float s1 = -1e30f;
#pragma unroll
            for (int e = 0; e < NE; e++) if (e != i0 && acc[e] > s1) { s1 = acc[e]; i1 = e; }
            float e1 = expf(s1 - s0);
            float inv = 1.f / (1.f + e1);
            g_tok_e[warp*2+0] = i0;  g_tok_w[warp*2+0] = inv;
            g_tok_e[warp*2+1] = i1;  g_tok_w[warp*2+1] = e1 * inv;
            atomicAdd(&g_counts[i0], 1);
            atomicAdd(&g_counts[i1], 1);
        }
    } else if (b < 1024) {
        int idx = (b - 512) * 256 + threadIdx.x;
        int n8 = T * DIM / 8;
        for (int i = idx; i < n8; i += 131072) {
            float4 v0 = ((const float4*)x)[i*2+0];
            float4 v1 = ((const float4*)x)[i*2+1];
            __align__(16) __half h[8];
            h[0]=__float2half(v0.x); h[1]=__float2half(v0.y);
            h[2]=__float2half(v0.z); h[3]=__float2half(v0.w);
            h[4]=__float2half(v1.x); h[5]=__float2half(v1.y);
            h[6]=__float2half(v1.z); h[7]=__float2half(v1.w);
            ((uint4*)g_Xh)[i] = *(uint4*)h;
        }
    } else {
        int idx = (b - 1024) * 256 + threadIdx.x;
        int n4 = T * DIM / 4;
        uint4 z = make_uint4(0,0,0,0);
        for (int i = idx; i < n4; i += 131072)
            ((uint4*)out)[i] = z;
    }
}

// ---------------- fused transpose + fp16 convert + scatter tail ----------------
__global__ __launch_bounds__(256) void k_transpose_all(
    const float* __restrict__ W1, const float* __restrict__ W3,
    const float* __restrict__ W2, int T)
{
    __shared__ float tile[64][65];
    int bid = blockIdx.x;

    if (bid >= 12288) {
        int t = (bid - 12288) * 256 + threadIdx.x;
        if (t >= T) return;
#pragma unroll
        for (int k = 0; k < 2; k++) {
            int e = g_tok_e[t*2+k];
            int pos = atomicAdd(&g_fill[e], 1);
            int slot = expert_base(e) + pos;
            g_slot_tok[slot] = t;
            g_slot_w[slot]   = g_tok_w[t*2+k];
        }
        return;
    }

    int sel = bid >> 12;
    int t   = bid & 4095;
    const float* in; __half* out; int R, C, tx, ty;
    if (sel < 2) {
        R = DIM; C = HID;
        int e = t >> 9; int tt = t & 511;
        tx = tt & 31; ty = tt >> 5;
        in  = (sel == 0 ? W1 : W3) + (size_t)e * R * C;
        out = (sel == 0 ? g_W1T : g_W3T) + (size_t)e * R * C;
    } else {
        R = HID; C = DIM;
        int e = t >> 9; int tt = t & 511;
        tx = tt & 15; ty = tt >> 4;
        in  = W2 + (size_t)e * R * C;
        out = g_W2T + (size_t)e * R * C;
    }
    int x0 = tx * 64, y0 = ty * 64;
    int tid = threadIdx.x;
#pragma unroll
    for (int i = 0; i < 4; i++) {
        int task = tid + 256 * i;
        int r = task >> 4, c4 = task & 15;
        float4 v = *(const float4*)(in + (size_t)(y0 + r) * C + x0 + c4 * 4);
        tile[r][c4*4+0] = v.x; tile[r][c4*4+1] = v.y;
        tile[r][c4*4+2] = v.z; tile[r][c4*4+3] = v.w;
    }
    __syncthreads();
#pragma unroll
    for (int i = 0; i < 2; i++) {
        int task = tid + 256 * i;
        int rr = task >> 3, c8 = task & 7;
        __align__(16) __half h[8];
#pragma unroll
        for (int j = 0; j < 8; j++)
            h[j] = __float2half(tile[c8*8+j][rr]);
        *(uint4*)(out + (size_t)(x0 + rr) * R + y0 + c8 * 8) = *(uint4*)h;
    }
}

// ================= GEMM1: H = silu(Xg@W1) * (Xg@W3) =================
#define G1_STAGE 32768
#define G1_SMEM  (3*G1_STAGE + 512)

__global__ __launch_bounds__(256, 2) void k_mma1() {
    extern __shared__ char smem[];
    int e    = blockIdx.y >> 5;
    int rt   = blockIdx.y & 31;
    int n_e  = g_counts[e];
    int row0 = rt * 128;
    if (row0 >= n_e) return;
    int base = expert_base(e);
    int col0 = blockIdx.x * 64;

    uint32_t sb = smem_u32(smem);
    int tid = threadIdx.x, wid = tid >> 5, lane = tid & 31;
    int wm = wid >> 1, wn = wid & 1;
    int gid = lane >> 2, ctid = lane & 3;
    int* toks = (int*)(smem + 3*G1_STAGE);

    if (tid < 128) {
        int r = row0 + tid;
        toks[tid] = (r < n_e) ? g_slot_tok[base + r] : -1;
    }
    __syncthreads();

    const __half* B1g = g_W1T + (size_t)e * HID * DIM + (size_t)col0 * DIM;
    const __half* B3g = g_W3T + (size_t)e * HID * DIM + (size_t)col0 * DIM;

    float acc1[2][4][4] = {}, acc3[2][4][4] = {};
    const int KT = DIM / 64;

    // ---- precomputed prefetch bases (affine in k0) ----
    const __half* aSrc[4]; uint32_t aDst[4]; int aSz[4];
#pragma unroll
    for (int s = 0; s < 4; s++) {
        int task = tid + 256 * s;
        int r = task >> 3, c = task & 7;
        int tok = toks[r];
        aSrc[s] = g_Xh + (size_t)(tok < 0 ? 0 : tok) * DIM + c * 8;
        aSz[s]  = tok < 0 ? 0 : 16;
        aDst[s] = r * 128 + ((c ^ (r & 7)) << 4);
    }
    size_t bOff[2]; uint32_t bDst[2];
#pragma unroll
    for (int i = 0; i < 2; i++) {
        int task = tid + 256 * i;
        int r = task >> 3, c = task & 7;
        bOff[i] = (size_t)r * DIM + c * 8;
        bDst[i] = r * 128 + ((c ^ (r & 7)) << 4);
    }

    // prime 2 stages
#pragma unroll
    for (int p = 0; p < 2; p++) {
        int k0 = p * 64;
        uint32_t sA  = sb + p * G1_STAGE;
        uint32_t sB1 = sA + 16384;
        uint32_t sB3 = sA + 24576;
#pragma unroll
        for (int s = 0; s < 4; s++) cpa16(sA + aDst[s], aSrc[s] + k0, aSz[s]);
#pragma unroll
        for (int i = 0; i < 2; i++) {
            cpa16(sB1 + bDst[i], B1g + bOff[i] + k0, 16);
            cpa16(sB3 + bDst[i], B3g + bOff[i] + k0, 16);
        }
        CP_COMMIT();
    }

    int arow = (lane & 15);
    int achk = (lane >> 4);
    uint32_t aBase[2], aSw[2], bBase[2], bSw[2];
#pragma unroll
    for (int mt = 0; mt < 2; mt++) {
        int row = wm * 32 + mt * 16 + arow;
        aBase[mt] = row * 128; aSw[mt] = row & 7;
    }
#pragma unroll
    for (int pr = 0; pr < 2; pr++) {
        int row = wn * 32 + pr * 16 + arow;
        bBase[pr] = row * 128; bSw[pr] = row & 7;
    }

    for (int kt = 0; kt < KT; kt++) {
        CP_WAIT1();
        __syncthreads();

        uint32_t sA  = sb + (kt % 3) * G1_STAGE;
        uint32_t sB1 = sA + 16384;
        uint32_t sB3 = sA + 24576;

        bool pf = (kt + 2 < KT);
        int k0pf = (kt + 2) * 64;
        uint32_t pA  = sb + ((kt + 2) % 3) * G1_STAGE;
        uint32_t pB1 = pA + 16384;
        uint32_t pB3 = pA + 24576;

#pragma unroll
        for (int s = 0; s < 4; s++) {
            int cb = s * 2 + achk;
            uint32_t aF[2][4], b1F[4][2], b3F[4][2];
            // A + B1 fragments first
#pragma unroll
            for (int mt = 0; mt < 2; mt++)
                LDSM4(aF[mt], sA + aBase[mt] + ((cb ^ aSw[mt]) << 4));
#pragma unroll
            for (int pr = 0; pr < 2; pr++) {
                uint32_t t1[4];
                LDSM4(t1, sB1 + bBase[pr] + ((cb ^ bSw[pr]) << 4));
                b1F[pr*2+0][0] = t1[0]; b1F[pr*2+0][1] = t1[2];
                b1F[pr*2+1][0] = t1[1]; b1F[pr*2+1][1] = t1[3];
            }
            // prefetch A slice in the shadow
            if (pf) cpa16(pA + aDst[s], aSrc[s] + k0pf, aSz[s]);
            // W1 MMAs while B3 fragments load
#pragma unroll
            for (int mt = 0; mt < 2; mt++)
#pragma unroll
                for (int nt = 0; nt < 4; nt++)
                    MMA_F16(acc1[mt][nt], aF[mt], b1F[nt]);
#pragma unroll
            for (int pr = 0; pr < 2; pr++) {
                uint32_t t3[4];
                LDSM4(t3, sB3 + bBase[pr] + ((cb ^ bSw[pr]) << 4));
                b3F[pr*2+0][0] = t3[0]; b3F[pr*2+0][1] = t3[2];
                b3F[pr*2+1][0] = t3[1]; b3F[pr*2+1][1] = t3[3];
            }
            // prefetch B slice in the shadow
            if (pf) {
                if (s < 2)
                    cpa16(pB1 + bDst[s], B1g + bOff[s] + k0pf, 16);
                else
                    cpa16(pB3 + bDst[s-2], B3g + bOff[s-2] + k0pf, 16);
            }
#pragma unroll
            for (int mt = 0; mt < 2; mt++)
#pragma unroll
                for (int nt = 0; nt < 4; nt++)
                    MMA_F16(acc3[mt][nt], aF[mt], b3F[nt]);
        }
        CP_COMMIT();
    }
    CP_WAIT0();

#pragma unroll
    for (int mt = 0; mt < 2; mt++) {
#pragma unroll
        for (int half = 0; half < 2; half++) {
            int r = row0 + wm * 32 + mt * 16 + half * 8 + gid;
            if (r >= n_e) continue;
            __half* hrow = g_H + (size_t)(base + r) * HID + col0;
#pragma unroll
            for (int nt = 0; nt < 4; nt++) {
                float z1a = acc1[mt][nt][half*2+0], z1b = acc1[mt][nt][half*2+1];
                float z3a = acc3[mt][nt][half*2+0], z3b = acc3[mt][nt][half*2+1];
                float ha = z1a / (1.f + __expf(-z1a)) * z3a;
                float hb = z1b / (1.f + __expf(-z1b)) * z3b;
                *(__half2*)(hrow + wn * 32 + nt * 8 + ctid * 2) =
                    __floats2half2_rn(ha, hb);
            }
        }
    }
}

// ================= GEMM2: out[tok] += w * (H @ W2) =================
#define G2_STAGE 32768
#define G2_SMEM  (3*G2_STAGE)

__global__ __launch_bounds__(256, 2) void k_mma2(float* __restrict__ out) {
    extern __shared__ char smem[];
    int e    = blockIdx.y >> 5;
    int rt   = blockIdx.y & 31;
    int n_e  = g_counts[e];
    int row0 = rt * 128;
    if (row0 >= n_e) return;
    int base = expert_base(e);
    int col0 = blockIdx.x * 128;

    uint32_t sb = smem_u32(smem);
    int tid = threadIdx.x, wid = tid >> 5, lane = tid & 31;
    int wm = wid >> 1, wn = wid & 1;
    int gid = lane >> 2, ctid = lane & 3;

    const __half* Bg = g_W2T + (size_t)e * DIM * HID + (size_t)col0 * HID;

    float acc[2][8][4] = {};
    const int KT = HID / 64;

    // ---- precomputed prefetch bases ----
    const __half* aSrc[4]; uint32_t aDst[4]; int aSz[4];
    size_t bOff[4]; uint32_t bDst[4];
#pragma unroll
    for (int s = 0; s < 4; s++) {
        int task = tid + 256 * s;
        int r = task >> 3, c = task & 7;
        int rr = row0 + r;
        bool ok = (rr < n_e);
        aSrc[s] = g_H + (size_t)(base + (ok ? rr : 0)) * HID + c * 8;
        aSz[s]  = ok ? 16 : 0;
        aDst[s] = r * 128 + ((c ^ (r & 7)) << 4);
        bOff[s] = (size_t)r * HID + c * 8;
        bDst[s] = aDst[s];
    }

    // prime 2 stages
#pragma unroll
    for (int p = 0; p < 2; p++) {
        int k0 = p * 64;
        uint32_t sA = sb + p * G2_STAGE;
        uint32_t sB = sA + 16384;
#pragma unroll
        for (int s = 0; s < 4; s++) {
            cpa16(sA + aDst[s], aSrc[s] + k0, aSz[s]);
            cpa16(sB + bDst[s], Bg + bOff[s] + k0, 16);
        }
        CP_COMMIT();
    }

    int arow = (lane & 15);
    int achk = (lane >> 4);
    uint32_t aBase[2], aSw[2], bBase[4], bSw[4];
#pragma unroll
    for (int mt = 0; mt < 2; mt++) {
        int row = wm * 32 + mt * 16 + arow;
        aBase[mt] = row * 128; aSw[mt] = row & 7;
    }
#pragma unroll
    for (int pr = 0; pr < 4; pr++) {
        int row = wn * 64 + pr * 16 + arow;
        bBase[pr] = row * 128; bSw[pr] = row & 7;
    }

    for (int kt = 0; kt < KT; kt++) {
        CP_WAIT1();
        __syncthreads();

        uint32_t sA = sb + (kt % 3) * G2_STAGE;
        uint32_t sB = sA + 16384;

        bool pf = (kt + 2 < KT);
        int k0pf = (kt + 2) * 64;
        uint32_t pA = sb + ((kt + 2) % 3) * G2_STAGE;
        uint32_t pB = pA + 16384;

#pragma unroll
        for (int s = 0; s < 4; s++) {
            int cb = s * 2 + achk;
            uint32_t aF[2][4], bF[8][2];
            // A + first half of B fragments
#pragma unroll
            for (int mt = 0; mt < 2; mt++)
                LDSM4(aF[mt], sA + aBase[mt] + ((cb ^ aSw[mt]) << 4));
#pragma unroll
            for (int pr = 0; pr < 2; pr++) {
                uint32_t t[4];
                LDSM4(t, sB + bBase[pr] + ((cb ^ bSw[pr]) << 4));
                bF[pr*2+0][0] = t[0]; bF[pr*2+0][1] = t[2];
                bF[pr*2+1][0] = t[1]; bF[pr*2+1][1] = t[3];
            }
            if (pf) cpa16(pA + aDst[s], aSrc[s] + k0pf, aSz[s]);
            // first-half MMAs while second-half B loads
#pragma unroll
            for (int mt = 0; mt < 2; mt++)
#pragma unroll
                for (int nt = 0; nt < 4; nt++)
                    MMA_F16(acc[mt][nt], aF[mt], bF[nt]);
#pragma unroll
            for (int pr = 2; pr < 4; pr++) {
                uint32_t t[4];
                LDSM4(t, sB + bBase[pr] + ((cb ^ bSw[pr]) << 4));
                bF[pr*2+0][0] = t[0]; bF[pr*2+0][1] = t[2];
                bF[pr*2+1][0] = t[1]; bF[pr*2+1][1] = t[3];
            }
            if (pf) cpa16(pB + bDst[s], Bg + bOff[s] + k0pf, 16);
#pragma unroll
            for (int mt = 0; mt < 2; mt++)
#pragma unroll
                for (int nt = 4; nt < 8; nt++)
                    MMA_F16(acc[mt][nt], aF[mt], bF[nt]);
        }
        CP_COMMIT();
    }
    CP_WAIT0();

#pragma unroll
    for (int mt = 0; mt < 2; mt++) {
#pragma unroll
        for (int half = 0; half < 2; half++) {
            int r = row0 + wm * 32 + mt * 16 + half * 8 + gid;
            if (r >= n_e) continue;
            float w  = g_slot_w[base + r];
            int  tok = g_slot_tok[base + r];
            float* orow = out + (size_t)tok * DIM + col0;
#pragma unroll
            for (int nt = 0; nt < 8; nt++) {
                int c = wn * 64 + nt * 8 + ctid * 2;
                atomicAdd(&orow[c],     w * acc[mt][nt][half*2+0]);
                atomicAdd(&orow[c + 1], w * acc[mt][nt][half*2+1]);
            }
        }
    }
}

// ---------------- launch ----------------
extern "C" void kernel_launch(void* const* d_in, const int* in_sizes, int n_in,
                              void* d_out, int out_size)
{
    const float* x  = (const float*)d_in[0];
    const float* Wg = (const float*)d_in[1];
    const float* W1 = (const float*)d_in[2];
    const float* W3 = (const float*)d_in[3];
    const float* W2 = (const float*)d_in[4];
    float* out = (float*)d_out;
    int T = in_sizes[0] / DIM;

    cudaFuncSetAttribute(k_mma1, cudaFuncAttributeMaxDynamicSharedMemorySize, G1_SMEM);
    cudaFuncSetAttribute(k_mma2, cudaFuncAttributeMaxDynamicSharedMemorySize, G2_SMEM);

    k_zero_cnt<<<1, 32>>>();
    k_front<<<1536, 256>>>(x, Wg, out, T);
    k_transpose_all<<<12288 + (MAXT + 255) / 256, 256>>>(W1, W3, W2, T);

    k_mma1<<<dim3(HID/64, NE * (MAXT/128)), 256, G1_SMEM>>>();
    k_mma2<<<dim3(DIM/128, NE * (MAXT/128)), 256, G2_SMEM>>>(out);
}

// round 16
// speedup vs baseline: 1.0296x; 1.0296x over previous
#include <cuda_runtime.h>
#include <cuda_fp16.h>
#include <math.h>
#include <stdint.h>

#define DIM  1024
#define HID  2048
#define NE   8
#define MAXT 4096
#define MAXSLOTS (MAXT*2)

// ---------------- device scratch ----------------
__device__ int    g_counts[NE];
__device__ int    g_fill[NE];
__device__ int    g_tok_e[MAXT*2];
__device__ float  g_tok_w[MAXT*2];
__device__ int    g_slot_tok[MAXSLOTS];
__device__ float  g_slot_w[MAXSLOTS];
__device__ __half g_Xh[(size_t)MAXT*DIM];
__device__ __half g_H[(size_t)MAXSLOTS*HID];
__device__ __half g_W1T[(size_t)NE*HID*DIM];    // [E][HID][DIM] k-major
__device__ __half g_W3T[(size_t)NE*HID*DIM];
__device__ __half g_W2T[(size_t)NE*DIM*HID];    // [E][DIM][HID] k-major

// ---------------- helpers ----------------
__device__ __forceinline__ uint32_t smem_u32(const void* p) {
    uint32_t a;
    asm("{ .reg .u64 t; cvta.to.shared.u64 t, %1; cvt.u32.u64 %0, t; }" : "=r"(a) : "l"(p));
    return a;
}
__device__ __forceinline__ void cpa16(uint32_t dst, const void* src, int sz) {
    asm volatile("cp.async.cg.shared.global [%0], [%1], 16, %2;"
                 :: "r"(dst), "l"(src), "r"(sz) : "memory");
}
#define CP_COMMIT() asm volatile("cp.async.commit_group;" ::: "memory")
#define CP_WAIT1()  asm volatile("cp.async.wait_group 1;" ::: "memory")
#define CP_WAIT0()  asm volatile("cp.async.wait_group 0;" ::: "memory")

#define LDSM4(r, addr) \
    asm volatile("ldmatrix.sync.aligned.m8n8.x4.shared.b16 {%0,%1,%2,%3}, [%4];" \
        : "=r"((r)[0]), "=r"((r)[1]), "=r"((r)[2]), "=r"((r)[3]) : "r"(addr))

#define MMA_F16(d, a, b) \
    asm volatile("mma.sync.aligned.m16n8k16.row.col.f32.f16.f16.f32 " \
        "{%0,%1,%2,%3}, {%4,%5,%6,%7}, {%8,%9}, {%0,%1,%2,%3};" \
        : "+f"((d)[0]), "+f"((d)[1]), "+f"((d)[2]), "+f"((d)[3]) \
        : "r"((a)[0]), "r"((a)[1]), "r"((a)[2]), "r"((a)[3]), \
          "r"((b)[0]), "r"((b)[1]))

__device__ __forceinline__ int expert_base(int e) {
    int b = 0;
#pragma unroll
    for (int i = 0; i < NE; i++) b += (i < e) ? g_counts[i] : 0;
    return b;
}

__global__ void k_zero_cnt() {
    if (threadIdx.x < NE) { g_counts[threadIdx.x] = 0; g_fill[threadIdx.x] = 0; }
}

// ---------------- fused front: zero out, cvt x->fp16, route ----------------
__global__ __launch_bounds__(256) void k_front(
    const float* __restrict__ x, const float* __restrict__ Wg,
    float* __restrict__ out, int T)
{
    int b = blockIdx.x;
    if (b < 512) {
        int warp = (b * 256 + threadIdx.x) >> 5;
        int lane = threadIdx.x & 31;
        if (warp >= T) return;
        const float* xr = x + (size_t)warp * DIM;
        float acc[NE];
#pragma unroll
        for (int e = 0; e < NE; e++) acc[e] = 0.f;
        for (int i = lane; i < DIM; i += 32) {
            float xv = xr[i];
            const float* wg = Wg + (size_t)i * NE;
#pragma unroll
            for (int e = 0; e < NE; e++) acc[e] += xv * wg[e];
        }
#pragma unroll
        for (int off = 16; off > 0; off >>= 1)
#pragma unroll
            for (int e = 0; e < NE; e++)
                acc[e] += __shfl_down_sync(0xffffffffu, acc[e], off);
        if (lane == 0) {
            int i0 = 0; float s0 = acc[0];
#pragma unroll
            for (int e = 1; e < NE; e++) if (acc[e] > s0) { s0 = acc[e]; i0 = e; }
            int i1 = -1; float s1 = -1e30f;
#pragma unroll
            for (int e = 0; e < NE; e++) if (e != i0 && acc[e] > s1) { s1 = acc[e]; i1 = e; }
            float e1 = expf(s1 - s0);
            float inv = 1.f / (1.f + e1);
            g_tok_e[warp*2+0] = i0;  g_tok_w[warp*2+0] = inv;
            g_tok_e[warp*2+1] = i1;  g_tok_w[warp*2+1] = e1 * inv;
            atomicAdd(&g_counts[i0], 1);
            atomicAdd(&g_counts[i1], 1);
        }
    } else if (b < 1024) {
        int idx = (b - 512) * 256 + threadIdx.x;
        int n8 = T * DIM / 8;
        for (int i = idx; i < n8; i += 131072) {
            float4 v0 = ((const float4*)x)[i*2+0];
            float4 v1 = ((const float4*)x)[i*2+1];
            __align__(16) __half h[8];
            h[0]=__float2half(v0.x); h[1]=__float2half(v0.y);
            h[2]=__float2half(v0.z); h[3]=__float2half(v0.w);
            h[4]=__float2half(v1.x); h[5]=__float2half(v1.y);
            h[6]=__float2half(v1.z); h[7]=__float2half(v1.w);
            ((uint4*)g_Xh)[i] = *(uint4*)h;
        }
    } else {
        int idx = (b - 1024) * 256 + threadIdx.x;
        int n4 = T * DIM / 4;
        uint4 z = make_uint4(0,0,0,0);
        for (int i = idx; i < n4; i += 131072)
            ((uint4*)out)[i] = z;
    }
}

// ---------------- fused transpose + fp16 convert + scatter tail ----------------
__global__ __launch_bounds__(256) void k_transpose_all(
    const float* __restrict__ W1, const float* __restrict__ W3,
    const float* __restrict__ W2, int T)
{
    __shared__ float tile[64][65];
    int bid = blockIdx.x;

    if (bid >= 12288) {
        int t = (bid - 12288) * 256 + threadIdx.x;
        if (t >= T) return;
#pragma unroll
        for (int k = 0; k < 2; k++) {
            int e = g_tok_e[t*2+k];
            int pos = atomicAdd(&g_fill[e], 1);
            int slot = expert_base(e) + pos;
            g_slot_tok[slot] = t;
            g_slot_w[slot]   = g_tok_w[t*2+k];
        }
        return;
    }

    int sel = bid >> 12;
    int t   = bid & 4095;
    const float* in; __half* out; int R, C, tx, ty;
    if (sel < 2) {
        R = DIM; C = HID;
        int e = t >> 9; int tt = t & 511;
        tx = tt & 31; ty = tt >> 5;
        in  = (sel == 0 ? W1 : W3) + (size_t)e * R * C;
        out = (sel == 0 ? g_W1T : g_W3T) + (size_t)e * R * C;
    } else {
        R = HID; C = DIM;
        int e = t >> 9; int tt = t & 511;
        tx = tt & 15; ty = tt >> 4;
        in  = W2 + (size_t)e * R * C;
        out = g_W2T + (size_t)e * R * C;
    }
    int x0 = tx * 64, y0 = ty * 64;
    int tid = threadIdx.x;
#pragma unroll
    for (int i = 0; i < 4; i++) {
        int task = tid + 256 * i;
        int r = task >> 4, c4 = task & 15;
        float4 v = *(const float4*)(in + (size_t)(y0 + r) * C + x0 + c4 * 4);
        tile[r][c4*4+0] = v.x; tile[r][c4*4+1] = v.y;
        tile[r][c4*4+2] = v.z; tile[r][c4*4+3] = v.w;
    }
    __syncthreads();
#pragma unroll
    for (int i = 0; i < 2; i++) {
        int task = tid + 256 * i;
        int rr = task >> 3, c8 = task & 7;
        __align__(16) __half h[8];
#pragma unroll
        for (int j = 0; j < 8; j++)
            h[j] = __float2half(tile[c8*8+j][rr]);
        *(uint4*)(out + (size_t)(x0 + rr) * R + y0 + c8 * 8) = *(uint4*)h;
    }
}

// ================= GEMM1: H = silu(Xg@W1) * (Xg@W3) =================
#define G1_STAGE 32768
#define G1_SMEM  (3*G1_STAGE + 512)

__global__ __launch_bounds__(256, 2) void k_mma1() {
    extern __shared__ char smem[];
    int e    = blockIdx.y >> 5;
    int rt   = blockIdx.y & 31;
    int n_e  = g_counts[e];
    int row0 = rt * 128;
    if (row0 >= n_e) return;
    int base = expert_base(e);
    int col0 = blockIdx.x * 64;

    uint32_t sb = smem_u32(smem);
    int tid = threadIdx.x, wid = tid >> 5, lane = tid & 31;
    int wm = wid >> 1, wn = wid & 1;
    int gid = lane >> 2, ctid = lane & 3;
    int* toks = (int*)(smem + 3*G1_STAGE);

    if (tid < 128) {
        int r = row0 + tid;
        toks[tid] = (r < n_e) ? g_slot_tok[base + r] : -1;
    }
    __syncthreads();

    const __half* B1g = g_W1T + (size_t)e * HID * DIM + (size_t)col0 * DIM;
    const __half* B3g = g_W3T + (size_t)e * HID * DIM + (size_t)col0 * DIM;

    float acc1[2][4][4] = {}, acc3[2][4][4] = {};
    const int KT = DIM / 64;

    // ---- precomputed prefetch bases (affine in k0) ----
    const __half* aSrc[4]; uint32_t aDst[4]; int aSz[4];
#pragma unroll
    for (int s = 0; s < 4; s++) {
        int task = tid + 256 * s;
        int r = task >> 3, c = task & 7;
        int tok = toks[r];
        aSrc[s] = g_Xh + (size_t)(tok < 0 ? 0 : tok) * DIM + c * 8;
        aSz[s]  = tok < 0 ? 0 : 16;
        aDst[s] = r * 128 + ((c ^ (r & 7)) << 4);
    }
    size_t bOff[2]; uint32_t bDst[2];
#pragma unroll
    for (int i = 0; i < 2; i++) {
        int task = tid + 256 * i;
        int r = task >> 3, c = task & 7;
        bOff[i] = (size_t)r * DIM + c * 8;
        bDst[i] = r * 128 + ((c ^ (r & 7)) << 4);
    }

    // prime 2 stages
#pragma unroll
    for (int p = 0; p < 2; p++) {
        int k0 = p * 64;
        uint32_t sA  = sb + p * G1_STAGE;
        uint32_t sB1 = sA + 16384;
        uint32_t sB3 = sA + 24576;
#pragma unroll
        for (int s = 0; s < 4; s++) cpa16(sA + aDst[s], aSrc[s] + k0, aSz[s]);
#pragma unroll
        for (int i = 0; i < 2; i++) {
            cpa16(sB1 + bDst[i], B1g + bOff[i] + k0, 16);
            cpa16(sB3 + bDst[i], B3g + bOff[i] + k0, 16);
        }
        CP_COMMIT();
    }

    int arow = (lane & 15);
    int achk = (lane >> 4);
    uint32_t aBase[2], aSw[2], bBase[2], bSw[2];
#pragma unroll
    for (int mt = 0; mt < 2; mt++) {
        int row = wm * 32 + mt * 16 + arow;
        aBase[mt] = row * 128; aSw[mt] = row & 7;
    }
#pragma unroll
    for (int pr = 0; pr < 2; pr++) {
        int row = wn * 32 + pr * 16 + arow;
        bBase[pr] = row * 128; bSw[pr] = row & 7;
    }

    for (int kt = 0; kt < KT; kt++) {
        CP_WAIT1();
        __syncthreads();

        uint32_t sA  = sb + (kt % 3) * G1_STAGE;
        uint32_t sB1 = sA + 16384;
        uint32_t sB3 = sA + 24576;

        bool pf = (kt + 2 < KT);
        int k0pf = (kt + 2) * 64;
        uint32_t pA  = sb + ((kt + 2) % 3) * G1_STAGE;
        uint32_t pB1 = pA + 16384;
        uint32_t pB3 = pA + 24576;

#pragma unroll
        for (int s = 0; s < 4; s++) {
            int cb = s * 2 + achk;
            uint32_t aF[2][4], b1F[4][2], b3F[4][2];
#pragma unroll
            for (int mt = 0; mt < 2; mt++)
                LDSM4(aF[mt], sA + aBase[mt] + ((cb ^ aSw[mt]) << 4));
#pragma unroll
            for (int pr = 0; pr < 2; pr++) {
                uint32_t off = bBase[pr] + ((cb ^ bSw[pr]) << 4);
                uint32_t t1[4], t3[4];
                LDSM4(t1, sB1 + off);
                LDSM4(t3, sB3 + off);
                b1F[pr*2+0][0] = t1[0]; b1F[pr*2+0][1] = t1[2];
                b1F[pr*2+1][0] = t1[1]; b1F[pr*2+1][1] = t1[3];
                b3F[pr*2+0][0] = t3[0]; b3F[pr*2+0][1] = t3[2];
                b3F[pr*2+1][0] = t3[1]; b3F[pr*2+1][1] = t3[3];
            }
            // interleaved prefetch with precomputed bases (single add per op)
            if (pf) {
                cpa16(pA + aDst[s], aSrc[s] + k0pf, aSz[s]);
                if (s < 2)
                    cpa16(pB1 + bDst[s], B1g + bOff[s] + k0pf, 16);
                else
                    cpa16(pB3 + bDst[s-2], B3g + bOff[s-2] + k0pf, 16);
            }
#pragma unroll
            for (int mt = 0; mt < 2; mt++)
#pragma unroll
                for (int nt = 0; nt < 4; nt++) {
                    MMA_F16(acc1[mt][nt], aF[mt], b1F[nt]);
                    MMA_F16(acc3[mt][nt], aF[mt], b3F[nt]);
                }
        }
        CP_COMMIT();
    }
    CP_WAIT0();

#pragma unroll
    for (int mt = 0; mt < 2; mt++) {
#pragma unroll
        for (int half = 0; half < 2; half++) {
            int r = row0 + wm * 32 + mt * 16 + half * 8 + gid;
            if (r >= n_e) continue;
            __half* hrow = g_H + (size_t)(base + r) * HID + col0;
#pragma unroll
            for (int nt = 0; nt < 4; nt++) {
                float z1a = acc1[mt][nt][half*2+0], z1b = acc1[mt][nt][half*2+1];
                float z3a = acc3[mt][nt][half*2+0], z3b = acc3[mt][nt][half*2+1];
                float ha = z1a / (1.f + __expf(-z1a)) * z3a;
                float hb = z1b / (1.f + __expf(-z1b)) * z3b;
                *(__half2*)(hrow + wn * 32 + nt * 8 + ctid * 2) =
                    __floats2half2_rn(ha, hb);
            }
        }
    }
}

// ================= GEMM2: out[tok] += w * (H @ W2) =================
#define G2_STAGE 32768
#define G2_SMEM  (3*G2_STAGE)

__global__ __launch_bounds__(256, 2) void k_mma2(float* __restrict__ out) {
    extern __shared__ char smem[];
    int e    = blockIdx.y >> 5;
    int rt   = blockIdx.y & 31;
    int n_e  = g_counts[e];
    int row0 = rt * 128;
    if (row0 >= n_e) return;
    int base = expert_base(e);
    int col0 = blockIdx.x * 128;

    uint32_t sb = smem_u32(smem);
    int tid = threadIdx.x, wid = tid >> 5, lane = tid & 31;
    int wm = wid >> 1, wn = wid & 1;
    int gid = lane >> 2, ctid = lane & 3;

    const __half* Bg = g_W2T + (size_t)e * DIM * HID + (size_t)col0 * HID;

    float acc[2][8][4] = {};
    const int KT = HID / 64;

    // ---- precomputed prefetch bases ----
    const __half* aSrc[4]; uint32_t aDst[4]; int aSz[4];
    size_t bOff[4]; uint32_t bDst[4];
#pragma unroll
    for (int s = 0; s < 4; s++) {
        int task = tid + 256 * s;
        int r = task >> 3, c = task & 7;
        int rr = row0 + r;
        bool ok = (rr < n_e);
        aSrc[s] = g_H + (size_t)(base + (ok ? rr : 0)) * HID + c * 8;
        aSz[s]  = ok ? 16 : 0;
        aDst[s] = r * 128 + ((c ^ (r & 7)) << 4);
        bOff[s] = (size_t)r * HID + c * 8;
        bDst[s] = aDst[s];
    }

    // prime 2 stages
#pragma unroll
    for (int p = 0; p < 2; p++) {
        int k0 = p * 64;
        uint32_t sA = sb + p * G2_STAGE;
        uint32_t sB = sA + 16384;
#pragma unroll
        for (int s = 0; s < 4; s++) {
            cpa16(sA + aDst[s], aSrc[s] + k0, aSz[s]);
            cpa16(sB + bDst[s], Bg + bOff[s] + k0, 16);
        }
        CP_COMMIT();
    }

    int arow = (lane & 15);
    int achk = (lane >> 4);
    uint32_t aBase[2], aSw[2], bBase[4], bSw[4];
#pragma unroll
    for (int mt = 0; mt < 2; mt++) {
        int row = wm * 32 + mt * 16 + arow;
        aBase[mt] = row * 128; aSw[mt] = row & 7;
    }
#pragma unroll
    for (int pr = 0; pr < 4; pr++) {
        int row = wn * 64 + pr * 16 + arow;
        bBase[pr] = row * 128; bSw[pr] = row & 7;
    }

    for (int kt = 0; kt < KT; kt++) {
        CP_WAIT1();
        __syncthreads();

        uint32_t sA = sb + (kt % 3) * G2_STAGE;
        uint32_t sB = sA + 16384;

        bool pf = (kt + 2 < KT);
        int k0pf = (kt + 2) * 64;
        uint32_t pA = sb + ((kt + 2) % 3) * G2_STAGE;
        uint32_t pB = pA + 16384;

#pragma unroll
        for (int s = 0; s < 4; s++) {
            int cb = s * 2 + achk;
            uint32_t aF[2][4], bF[8][2];
#pragma unroll
            for (int mt = 0; mt < 2; mt++)
                LDSM4(aF[mt], sA + aBase[mt] + ((cb ^ aSw[mt]) << 4));
#pragma unroll
            for (int pr = 0; pr < 4; pr++) {
                uint32_t t[4];
                LDSM4(t, sB + bBase[pr] + ((cb ^ bSw[pr]) << 4));
                bF[pr*2+0][0] = t[0]; bF[pr*2+0][1] = t[2];
                bF[pr*2+1][0] = t[1]; bF[pr*2+1][1] = t[3];
            }
            if (pf) {
                cpa16(pA + aDst[s], aSrc[s] + k0pf, aSz[s]);
                cpa16(pB + bDst[s], Bg + bOff[s] + k0pf, 16);
            }
#pragma unroll
            for (int mt = 0; mt < 2; mt++)
#pragma unroll
                for (int nt = 0; nt < 8; nt++)
                    MMA_F16(acc[mt][nt], aF[mt], bF[nt]);
        }
        CP_COMMIT();
    }
    CP_WAIT0();

#pragma unroll
    for (int mt = 0; mt < 2; mt++) {
#pragma unroll
        for (int half = 0; half < 2; half++) {
            int r = row0 + wm * 32 + mt * 16 + half * 8 + gid;
            if (r >= n_e) continue;
            float w  = g_slot_w[base + r];
            int  tok = g_slot_tok[base + r];
            float* orow = out + (size_t)tok * DIM + col0;
#pragma unroll
            for (int nt = 0; nt < 8; nt++) {
                int c = wn * 64 + nt * 8 + ctid * 2;
                atomicAdd(&orow[c],     w * acc[mt][nt][half*2+0]);
                atomicAdd(&orow[c + 1], w * acc[mt][nt][half*2+1]);
            }
        }
    }
}

// ---------------- launch ----------------
extern "C" void kernel_launch(void* const* d_in, const int* in_sizes, int n_in,
                              void* d_out, int out_size)
{
    const float* x  = (const float*)d_in[0];
    const float* Wg = (const float*)d_in[1];
    const float* W1 = (const float*)d_in[2];
    const float* W3 = (const float*)d_in[3];
    const float* W2 = (const float*)d_in[4];
    float* out = (float*)d_out;
    int T = in_sizes[0] / DIM;

    cudaFuncSetAttribute(k_mma1, cudaFuncAttributeMaxDynamicSharedMemorySize, G1_SMEM);
    cudaFuncSetAttribute(k_mma2, cudaFuncAttributeMaxDynamicSharedMemorySize, G2_SMEM);

    k_zero_cnt<<<1, 32>>>();
    k_front<<<1536, 256>>>(x, Wg, out, T);
    k_transpose_all<<<12288 + (MAXT + 255) / 256, 256>>>(W1, W3, W2, T);

    k_mma1<<<dim3(HID/64, NE * (MAXT/128)), 256, G1_SMEM>>>();
    k_mma2<<<dim3(DIM/128, NE * (MAXT/128)), 256, G2_SMEM>>>(out);
}

// round 17
// speedup vs baseline: 1.0303x; 1.0007x over previous
#include <cuda_runtime.h>
#include <cuda_fp16.h>
#include <math.h>
#include <stdint.h>

#define DIM  1024
#define HID  2048
#define NE   8
#define MAXT 4096
#define MAXSLOTS (MAXT*2)

// ---------------- device scratch ----------------
__device__ int    g_counts[NE];
__device__ int    g_fill[NE];
__device__ int    g_tok_e[MAXT*2];
__device__ float  g_tok_w[MAXT*2];
__device__ int    g_slot_tok[MAXSLOTS];
__device__ float  g_slot_w[MAXSLOTS];
__device__ __half g_Xh[(size_t)MAXT*DIM];
__device__ __half g_H[(size_t)MAXSLOTS*HID];
__device__ __half g_W1T[(size_t)NE*HID*DIM];    // [E][HID][DIM] k-major
__device__ __half g_W3T[(size_t)NE*HID*DIM];
__device__ __half g_W2T[(size_t)NE*DIM*HID];    // [E][DIM][HID] k-major

// ---------------- helpers ----------------
__device__ __forceinline__ uint32_t smem_u32(const void* p) {
    uint32_t a;
    asm("{ .reg .u64 t; cvta.to.shared.u64 t, %1; cvt.u32.u64 %0, t; }" : "=r"(a) : "l"(p));
    return a;
}
__device__ __forceinline__ void cpa16(uint32_t dst, const void* src, int sz) {
    asm volatile("cp.async.cg.shared.global [%0], [%1], 16, %2;"
                 :: "r"(dst), "l"(src), "r"(sz) : "memory");
}
#define CP_COMMIT() asm volatile("cp.async.commit_group;" ::: "memory")
#define CP_WAIT1()  asm volatile("cp.async.wait_group 1;" ::: "memory")
#define CP_WAIT0()  asm volatile("cp.async.wait_group 0;" ::: "memory")

#define LDSM4(r, addr) \
    asm volatile("ldmatrix.sync.aligned.m8n8.x4.shared.b16 {%0,%1,%2,%3}, [%4];" \
        : "=r"((r)[0]), "=r"((r)[1]), "=r"((r)[2]), "=r"((r)[3]) : "r"(addr))

#define MMA_F16(d, a, b) \
    asm volatile("mma.sync.aligned.m16n8k16.row.col.f32.f16.f16.f32 " \
        "{%0,%1,%2,%3}, {%4,%5,%6,%7}, {%8,%9}, {%0,%1,%2,%3};" \
        : "+f"((d)[0]), "+f"((d)[1]), "+f"((d)[2]), "+f"((d)[3]) \
        : "r"((a)[0]), "r"((a)[1]), "r"((a)[2]), "r"((a)[3]), \
          "r"((b)[0]), "r"((b)[1]))

__device__ __forceinline__ int expert_base(int e) {
    int b = 0;
#pragma unroll
    for (int i = 0; i < NE; i++) b += (i < e) ? g_counts[i] : 0;
    return b;
}

__global__ void k_zero_cnt() {
    if (threadIdx.x < NE) { g_counts[threadIdx.x] = 0; g_fill[threadIdx.x] = 0; }
}

// ---------------- fused front: zero out, cvt x->fp16, route ----------------
__global__ __launch_bounds__(256) void k_front(
    const float* __restrict__ x, const float* __restrict__ Wg,
    float* __restrict__ out, int T)
{
    int b = blockIdx.x;
    if (b < 512) {
        int warp = (b * 256 + threadIdx.x) >> 5;
        int lane = threadIdx.x & 31;
        if (warp >= T) return;
        const float* xr = x + (size_t)warp * DIM;
        float acc[NE];
#pragma unroll
        for (int e = 0; e < NE; e++) acc[e] = 0.f;
        for (int i = lane; i < DIM; i += 32) {
            float xv = xr[i];
            const float* wg = Wg + (size_t)i * NE;
#pragma unroll
            for (int e = 0; e < NE; e++) acc[e] += xv * wg[e];
        }
#pragma unroll
        for (int off = 16; off > 0; off >>= 1)
#pragma unroll
            for (int e = 0; e < NE; e++)
                acc[e] += __shfl_down_sync(0xffffffffu, acc[e], off);
        if (lane == 0) {
            int i0 = 0; float s0 = acc[0];
#pragma unroll
            for (int e = 1; e < NE; e++) if (acc[e] > s0) { s0 = acc[e]; i0 = e; }
            int i1 = -1; float s1 = -1e30f;
#pragma unroll
            for (int e = 0; e < NE; e++) if (e != i0 && acc[e] > s1) { s1 = acc[e]; i1 = e; }
            float e1 = expf(s1 - s0);
            float inv = 1.f / (1.f + e1);
            g_tok_e[warp*2+0] = i0;  g_tok_w[warp*2+0] = inv;
            g_tok_e[warp*2+1] = i1;  g_tok_w[warp*2+1] = e1 * inv;
            atomicAdd(&g_counts[i0], 1);
            atomicAdd(&g_counts[i1], 1);
        }
    } else if (b < 1024) {
        int idx = (b - 512) * 256 + threadIdx.x;
        int n8 = T * DIM / 8;
        for (int i = idx; i < n8; i += 131072) {
            float4 v0 = ((const float4*)x)[i*2+0];
            float4 v1 = ((const float4*)x)[i*2+1];
            __align__(16) __half h[8];
            h[0]=__float2half(v0.x); h[1]=__float2half(v0.y);
            h[2]=__float2half(v0.z); h[3]=__float2half(v0.w);
            h[4]=__float2half(v1.x); h[5]=__float2half(v1.y);
            h[6]=__float2half(v1.z); h[7]=__float2half(v1.w);
            ((uint4*)g_Xh)[i] = *(uint4*)h;
        }
    } else {
        int idx = (b - 1024) * 256 + threadIdx.x;
        int n4 = T * DIM / 4;
        uint4 z = make_uint4(0,0,0,0);
        for (int i = idx; i < n4; i += 131072)
            ((uint4*)out)[i] = z;
    }
}

// ---------------- transpose W1/W3 + fp16 convert + scatter tail ----------------
// grid: [0,8192) W1/W3 tiles; [8192,8208) scatter
__global__ __launch_bounds__(256) void k_transpose_13(
    const float* __restrict__ W1, const float* __restrict__ W3, int T)
{
    __shared__ float tile[64][65];
    int bid = blockIdx.x;

    if (bid >= 8192) {
        int t = (bid - 8192) * 256 + threadIdx.x;
        if (t >= T) return;
#pragma unroll
        for (int k = 0; k < 2; k++) {
            int e = g_tok_e[t*2+k];
            int pos = atomicAdd(&g_fill[e], 1);
            int slot = expert_base(e) + pos;
            g_slot_tok[slot] = t;
            g_slot_w[slot]   = g_tok_w[t*2+k];
        }
        return;
    }

    int sel = bid >> 12;                 // 0: W1, 1: W3
    int t   = bid & 4095;
    const int R = DIM, C = HID;
    int e = t >> 9; int tt = t & 511;
    int tx = tt & 31, ty = tt >> 5;
    const float* in = (sel == 0 ? W1 : W3) + (size_t)e * R * C;
    __half* out = (sel == 0 ? g_W1T : g_W3T) + (size_t)e * R * C;

    int x0 = tx * 64, y0 = ty * 64;
    int tid = threadIdx.x;
#pragma unroll
    for (int i = 0; i < 4; i++) {
        int task = tid + 256 * i;
        int r = task >> 4, c4 = task & 15;
        float4 v = *(const float4*)(in + (size_t)(y0 + r) * C + x0 + c4 * 4);
        tile[r][c4*4+0] = v.x; tile[r][c4*4+1] = v.y;
        tile[r][c4*4+2] = v.z; tile[r][c4*4+3] = v.w;
    }
    __syncthreads();
#pragma unroll
    for (int i = 0; i < 2; i++) {
        int task = tid + 256 * i;
        int rr = task >> 3, c8 = task & 7;
        __align__(16) __half h[8];
#pragma unroll
        for (int j = 0; j < 8; j++)
            h[j] = __float2half(tile[c8*8+j][rr]);
        *(uint4*)(out + (size_t)(x0 + rr) * R + y0 + c8 * 8) = *(uint4*)h;
    }
}

// ================= GEMM1 (+ hidden W2 transpose blocks) =================
#define G1_STAGE 32768
#define G1_SMEM  (3*G1_STAGE + 512)

__global__ __launch_bounds__(256, 2) void k_mma1(const float* __restrict__ W2) {
    extern __shared__ char smem[];

    // ---- W2 transpose blocks: blockIdx.y in [256, 384) ----
    if (blockIdx.y >= 256) {
        float (*tile)[65] = (float(*)[65])smem;   // alias dynamic smem
        int t = (blockIdx.y - 256) * 32 + blockIdx.x;   // 0..4095
        const int R = HID, C = DIM;
        int e = t >> 9; int tt = t & 511;
        int tx = tt & 15, ty = tt >> 4;
        const float* in = W2 + (size_t)e * R * C;
        __half* out = g_W2T + (size_t)e * R * C;
        int x0 = tx * 64, y0 = ty * 64;
        int tid = threadIdx.x;
#pragma unroll
        for (int i = 0; i < 4; i++) {
            int task = tid + 256 * i;
            int r = task >> 4, c4 = task & 15;
            float4 v = *(const float4*)(in + (size_t)(y0 + r) * C + x0 + c4 * 4);
            tile[r][c4*4+0] = v.x; tile[r][c4*4+1] = v.y;
            tile[r][c4*4+2] = v.z; tile[r][c4*4+3] = v.w;
        }
        __syncthreads();
#pragma unroll
        for (int i = 0; i < 2; i++) {
            int task = tid + 256 * i;
            int rr = task >> 3, c8 = task & 7;
            __align__(16) __half h[8];
#pragma unroll
            for (int j = 0; j < 8; j++)
                h[j] = __float2half(tile[c8*8+j][rr]);
            *(uint4*)(out + (size_t)(x0 + rr) * R + y0 + c8 * 8) = *(uint4*)h;
        }
        return;
    }

    // ---- GEMM blocks ----
    int e    = blockIdx.y >> 5;
    int rt   = blockIdx.y & 31;
    int n_e  = g_counts[e];
    int row0 = rt * 128;
    if (row0 >= n_e) return;
    int base = expert_base(e);
    int col0 = blockIdx.x * 64;

    uint32_t sb = smem_u32(smem);
    int tid = threadIdx.x, wid = tid >> 5, lane = tid & 31;
    int wm = wid >> 1, wn = wid & 1;
    int gid = lane >> 2, ctid = lane & 3;
    int* toks = (int*)(smem + 3*G1_STAGE);

    if (tid < 128) {
        int r = row0 + tid;
        toks[tid] = (r < n_e) ? g_slot_tok[base + r] : -1;
    }
    __syncthreads();

    const __half* B1g = g_W1T + (size_t)e * HID * DIM + (size_t)col0 * DIM;
    const __half* B3g = g_W3T + (size_t)e * HID * DIM + (size_t)col0 * DIM;

    float acc1[2][4][4] = {}, acc3[2][4][4] = {};
    const int KT = DIM / 64;

    const __half* aSrc[4]; uint32_t aDst[4]; int aSz[4];
#pragma unroll
    for (int s = 0; s < 4; s++) {
        int task = tid + 256 * s;
        int r = task >> 3, c = task & 7;
        int tok = toks[r];
        aSrc[s] = g_Xh + (size_t)(tok < 0 ? 0 : tok) * DIM + c * 8;
        aSz[s]  = tok < 0 ? 0 : 16;
        aDst[s] = r * 128 + ((c ^ (r & 7)) << 4);
    }
    size_t bOff[2]; uint32_t bDst[2];
#pragma unroll
    for (int i = 0; i < 2; i++) {
        int task = tid + 256 * i;
        int r = task >> 3, c = task & 7;
        bOff[i] = (size_t)r * DIM + c * 8;
        bDst[i] = r * 128 + ((c ^ (r & 7)) << 4);
    }

#pragma unroll
    for (int p = 0; p < 2; p++) {
        int k0 = p * 64;
        uint32_t sA  = sb + p * G1_STAGE;
        uint32_t sB1 = sA + 16384;
        uint32_t sB3 = sA + 24576;
#pragma unroll
        for (int s = 0; s < 4; s++) cpa16(sA + aDst[s], aSrc[s] + k0, aSz[s]);
#pragma unroll
        for (int i = 0; i < 2; i++) {
            cpa16(sB1 + bDst[i], B1g + bOff[i] + k0, 16);
            cpa16(sB3 + bDst[i], B3g + bOff[i] + k0, 16);
        }
        CP_COMMIT();
    }

    int arow = (lane & 15);
    int achk = (lane >> 4);
    uint32_t aBase[2], aSw[2], bBase[2], bSw[2];
#pragma unroll
    for (int mt = 0; mt < 2; mt++) {
        int row = wm * 32 + mt * 16 + arow;
        aBase[mt] = row * 128; aSw[mt] = row & 7;
    }
#pragma unroll
    for (int pr = 0; pr < 2; pr++) {
        int row = wn * 32 + pr * 16 + arow;
        bBase[pr] = row * 128; bSw[pr] = row & 7;
    }

    for (int kt = 0; kt < KT; kt++) {
        CP_WAIT1();
        __syncthreads();

        uint32_t sA  = sb + (kt % 3) * G1_STAGE;
        uint32_t sB1 = sA + 16384;
        uint32_t sB3 = sA + 24576;

        bool pf = (kt + 2 < KT);
        int k0pf = (kt + 2) * 64;
        uint32_t pA  = sb + ((kt + 2) % 3) * G1_STAGE;
        uint32_t pB1 = pA + 16384;
        uint32_t pB3 = pA + 24576;

#pragma unroll
        for (int s = 0; s < 4; s++) {
            int cb = s * 2 + achk;
            uint32_t aF[2][4], b1F[4][2], b3F[4][2];
#pragma unroll
            for (int mt = 0; mt < 2; mt++)
                LDSM4(aF[mt], sA + aBase[mt] + ((cb ^ aSw[mt]) << 4));
#pragma unroll
            for (int pr = 0; pr < 2; pr++) {
                uint32_t off = bBase[pr] + ((cb ^ bSw[pr]) << 4);
                uint32_t t1[4], t3[4];
                LDSM4(t1, sB1 + off);
                LDSM4(t3, sB3 + off);
                b1F[pr*2+0][0] = t1[0]; b1F[pr*2+0][1] = t1[2];
                b1F[pr*2+1][0] = t1[1]; b1F[pr*2+1][1] = t1[3];
                b3F[pr*2+0][0] = t3[0]; b3F[pr*2+0][1] = t3[2];
                b3F[pr*2+1][0] = t3[1]; b3F[pr*2+1][1] = t3[3];
            }
            if (pf) {
                cpa16(pA + aDst[s], aSrc[s] + k0pf, aSz[s]);
                if (s < 2)
                    cpa16(pB1 + bDst[s], B1g + bOff[s] + k0pf, 16);
                else
                    cpa16(pB3 + bDst[s-2], B3g + bOff[s-2] + k0pf, 16);
            }
#pragma unroll
            for (int mt = 0; mt < 2; mt++)
#pragma unroll
                for (int nt = 0; nt < 4; nt++) {
                    MMA_F16(acc1[mt][nt], aF[mt], b1F[nt]);
                    MMA_F16(acc3[mt][nt], aF[mt], b3F[nt]);
                }
        }
        CP_COMMIT();
    }
    CP_WAIT0();

#pragma unroll
    for (int mt = 0; mt < 2; mt++) {
#pragma unroll
        for (int half = 0; half < 2; half++) {
            int r = row0 + wm * 32 + mt * 16 + half * 8 + gid;
            if (r >= n_e) continue;
            __half* hrow = g_H + (size_t)(base + r) * HID + col0;
#pragma unroll
            for (int nt = 0; nt < 4; nt++) {
                float z1a = acc1[mt][nt][half*2+0], z1b = acc1[mt][nt][half*2+1];
                float z3a = acc3[mt][nt][half*2+0], z3b = acc3[mt][nt][half*2+1];
                float ha = z1a / (1.f + __expf(-z1a)) * z3a;
                float hb = z1b / (1.f + __expf(-z1b)) * z3b;
                *(__half2*)(hrow + wn * 32 + nt * 8 + ctid * 2) =
                    __floats2half2_rn(ha, hb);
            }
        }
    }
}

// ================= GEMM2: out[tok] += w * (H @ W2) =================
#define G2_STAGE 32768
#define G2_SMEM  (3*G2_STAGE)

__global__ __launch_bounds__(256, 2) void k_mma2(float* __restrict__ out) {
    extern __shared__ char smem[];
    int e    = blockIdx.y >> 5;
    int rt   = blockIdx.y & 31;
    int n_e  = g_counts[e];
    int row0 = rt * 128;
    if (row0 >= n_e) return;
    int base = expert_base(e);
    int col0 = blockIdx.x * 128;

    uint32_t sb = smem_u32(smem);
    int tid = threadIdx.x, wid = tid >> 5, lane = tid & 31;
    int wm = wid >> 1, wn = wid & 1;
    int gid = lane >> 2, ctid = lane & 3;

    const __half* Bg = g_W2T + (size_t)e * DIM * HID + (size_t)col0 * HID;

    float acc[2][8][4] = {};
    const int KT = HID / 64;

    const __half* aSrc[4]; uint32_t aDst[4]; int aSz[4];
    size_t bOff[4]; uint32_t bDst[4];
#pragma unroll
    for (int s = 0; s < 4; s++) {
        int task = tid + 256 * s;
        int r = task >> 3, c = task & 7;
        int rr = row0 + r;
        bool ok = (rr < n_e);
        aSrc[s] = g_H + (size_t)(base + (ok ? rr : 0)) * HID + c * 8;
        aSz[s]  = ok ? 16 : 0;
        aDst[s] = r * 128 + ((c ^ (r & 7)) << 4);
        bOff[s] = (size_t)r * HID + c * 8;
        bDst[s] = aDst[s];
    }

#pragma unroll
    for (int p = 0; p < 2; p++) {
        int k0 = p * 64;
        uint32_t sA = sb + p * G2_STAGE;
        uint32_t sB = sA + 16384;
#pragma unroll
        for (int s = 0; s < 4; s++) {
            cpa16(sA + aDst[s], aSrc[s] + k0, aSz[s]);
            cpa16(sB + bDst[s], Bg + bOff[s] + k0, 16);
        }
        CP_COMMIT();
    }

    int arow = (lane & 15);
    int achk = (lane >> 4);
    uint32_t aBase[2], aSw[2], bBase[4], bSw[4];
#pragma unroll
    for (int mt = 0; mt < 2; mt++) {
        int row = wm * 32 + mt * 16 + arow;
        aBase[mt] = row * 128; aSw[mt] = row & 7;
    }
#pragma unroll
    for (int pr = 0; pr < 4; pr++) {
        int row = wn * 64 + pr * 16 + arow;
        bBase[pr] = row * 128; bSw[pr] = row & 7;
    }

    for (int kt = 0; kt < KT; kt++) {
        CP_WAIT1();
        __syncthreads();

        uint32_t sA = sb + (kt % 3) * G2_STAGE;
        uint32_t sB = sA + 16384;

        bool pf = (kt + 2 < KT);
        int k0pf = (kt + 2) * 64;
        uint32_t pA = sb + ((kt + 2) % 3) * G2_STAGE;
        uint32_t pB = pA + 16384;

#pragma unroll
        for (int s = 0; s < 4; s++) {
            int cb = s * 2 + achk;
            uint32_t aF[2][4], bF[8][2];
#pragma unroll
            for (int mt = 0; mt < 2; mt++)
                LDSM4(aF[mt], sA + aBase[mt] + ((cb ^ aSw[mt]) << 4));
#pragma unroll
            for (int pr = 0; pr < 4; pr++) {
                uint32_t t[4];
                LDSM4(t, sB + bBase[pr] + ((cb ^ bSw[pr]) << 4));
                bF[pr*2+0][0] = t[0]; bF[pr*2+0][1] = t[2];
                bF[pr*2+1][0] = t[1]; bF[pr*2+1][1] = t[3];
            }
            if (pf) {
                cpa16(pA + aDst[s], aSrc[s] + k0pf, aSz[s]);
                cpa16(pB + bDst[s], Bg + bOff[s] + k0pf, 16);
            }
#pragma unroll
            for (int mt = 0; mt < 2; mt++)
#pragma unroll
                for (int nt = 0; nt < 8; nt++)
                    MMA_F16(acc[mt][nt], aF[mt], bF[nt]);
        }
        CP_COMMIT();
    }
    CP_WAIT0();

#pragma unroll
    for (int mt = 0; mt < 2; mt++) {
#pragma unroll
        for (int half = 0; half < 2; half++) {
            int r = row0 + wm * 32 + mt * 16 + half * 8 + gid;
            if (r >= n_e) continue;
            float w  = g_slot_w[base + r];
            int  tok = g_slot_tok[base + r];
            float* orow = out + (size_t)tok * DIM + col0;
#pragma unroll
            for (int nt = 0; nt < 8; nt++) {
                int c = wn * 64 + nt * 8 + ctid * 2;
                atomicAdd(&orow[c],     w * acc[mt][nt][half*2+0]);
                atomicAdd(&orow[c + 1], w * acc[mt][nt][half*2+1]);
            }
        }
    }
}

// ---------------- launch ----------------
extern "C" void kernel_launch(void* const* d_in, const int* in_sizes, int n_in,
                              void* d_out, int out_size)
{
    const float* x  = (const float*)d_in[0];
    const float* Wg = (const float*)d_in[1];
    const float* W1 = (const float*)d_in[2];
    const float* W3 = (const float*)d_in[3];
    const float* W2 = (const float*)d_in[4];
    float* out = (float*)d_out;
    int T = in_sizes[0] / DIM;

    cudaFuncSetAttribute(k_mma1, cudaFuncAttributeMaxDynamicSharedMemorySize, G1_SMEM);
    cudaFuncSetAttribute(k_mma2, cudaFuncAttributeMaxDynamicSharedMemorySize, G2_SMEM);

    k_zero_cnt<<<1, 32>>>();
    k_front<<<1536, 256>>>(x, Wg, out, T);
    k_transpose_13<<<8192 + (MAXT + 255) / 256, 256>>>(W1, W3, T);

    // GEMM1 + W2 transpose hidden in extra y-blocks [256,384)
    k_mma1<<<dim3(HID/64, 256 + 128), 256, G1_SMEM>>>(W2);
    k_mma2<<<dim3(DIM/128, NE * (MAXT/128)), 256, G2_SMEM>>>(out);
}